// round 8
// baseline (speedup 1.0000x reference)
#include <cuda_runtime.h>
#include <cuda_fp16.h>
#include <cstdint>

#define NTOT   100000
#define KNEI   16
#define XNIN   128
#define XEIN   64
#define XNOUT  128
#define KTOT   320      // 128 (x) + 128 (xnj) + 64 (xej)
#define AS     328      // smem row stride in halves: bank = 4g+tg, conflict-free
#define CHUNK_ROWS 64
#define NCH    ((NTOT + CHUNK_ROWS - 1) / CHUNK_ROWS)   // 1563
#define GRID_G 152      // GB300: 152 SMs, 1 persistent CTA each

// Scratch (device globals — allocation-free per harness rules)
__device__ __half g_xh[(size_t)NTOT * XNIN];      // fp16 copy of x (25.6 MB)
__device__ __half g_A2[(size_t)NTOT * 192];       // fp16 [gather-mean(128) | e-mean(64)]
__device__ __half g_wh[XNOUT * KTOT];             // packed fp16 [Wc|Wn|We], row-major (n,k)

// ---------------------------------------------------------------------------
// Kernel 1: quantize x -> fp16, pack weights -> fp16
// ---------------------------------------------------------------------------
__global__ void prep_kernel(const float* __restrict__ x,
                            const float* __restrict__ Wc,
                            const float* __restrict__ Wn,
                            const float* __restrict__ We) {
    int tid = blockIdx.x * blockDim.x + threadIdx.x;
    int stride = gridDim.x * blockDim.x;

    const float4* x4 = (const float4*)x;
    __half2* xh2 = (__half2*)g_xh;
    const int total4 = NTOT * XNIN / 4;
    for (int i = tid; i < total4; i += stride) {
        float4 v = __ldcs(&x4[i]);
        xh2[2 * i]     = __floats2half2_rn(v.x, v.y);
        xh2[2 * i + 1] = __floats2half2_rn(v.z, v.w);
    }

    for (int i = tid; i < XNOUT * KTOT; i += stride) {
        int n = i / KTOT, k = i % KTOT;
        float w = (k < 128) ? Wc[n * 128 + k]
                : (k < 256) ? Wn[n * 128 + (k - 128)]
                            : We[n * 64 + (k - 256)];
        g_wh[i] = __float2half(w);
    }
}

// ---------------------------------------------------------------------------
// Kernel 2: build A2. Warp-specialized:
//   odd warps : e-mean streaming (DRAM-bound), 2 rows per iteration
//   even warps: x gather-mean (L2-bound),      2 rows per iteration
// ---------------------------------------------------------------------------
__global__ void __launch_bounds__(256)
build_kernel(const float* __restrict__ e,
             const int* __restrict__ ij) {
    const int lane  = threadIdx.x & 31;
    const int gwarp = (blockIdx.x * blockDim.x + threadIdx.x) >> 5;
    const int nW    = (gridDim.x * blockDim.x) >> 5;
    const int wid2  = gwarp >> 1;          // id within my type
    const int nT    = nW >> 1;             // warps of my type

    if (gwarp & 1) {
        // ================= e-mean warps =================
        for (int r = wid2; r < NTOT; r += 2 * nT) {
            const int rb = r + nT;
            float2 ea[KNEI], eb[KNEI];
            const float2* pa = (const float2*)(e + (size_t)r * (KNEI * XEIN)) + lane;
            #pragma unroll
            for (int k = 0; k < KNEI; k++) ea[k] = __ldcs(pa + k * (XEIN / 2));
            if (rb < NTOT) {
                const float2* pb = (const float2*)(e + (size_t)rb * (KNEI * XEIN)) + lane;
                #pragma unroll
                for (int k = 0; k < KNEI; k++) eb[k] = __ldcs(pb + k * (XEIN / 2));
            }

            float s0 = 0.f, s1 = 0.f;
            #pragma unroll
            for (int k = 0; k < KNEI; k++) { s0 += ea[k].x; s1 += ea[k].y; }
            *(__half2*)&g_A2[(size_t)r * 192 + 128 + lane * 2] =
                __floats2half2_rn(s0 * 0.0625f, s1 * 0.0625f);

            if (rb < NTOT) {
                float t0 = 0.f, t1 = 0.f;
                #pragma unroll
                for (int k = 0; k < KNEI; k++) { t0 += eb[k].x; t1 += eb[k].y; }
                *(__half2*)&g_A2[(size_t)rb * 192 + 128 + lane * 2] =
                    __floats2half2_rn(t0 * 0.0625f, t1 * 0.0625f);
            }
        }
    } else {
        // ================= gather warps =================
        int r = wid2;
        int idxA = 0, idxB = 0;
        if (r < NTOT && lane < KNEI)
            idxA = __ldcs(&ij[((size_t)r * KNEI + lane) * 2]);
        if (r + nT < NTOT && lane < KNEI)
            idxB = __ldcs(&ij[((size_t)(r + nT) * KNEI + lane) * 2]);

        for (; r < NTOT; r += 2 * nT) {
            const int rb = r + nT;
            // prefetch indices for next iteration
            const int rnA = r + 2 * nT, rnB = rb + 2 * nT;
            int idxA_n = 0, idxB_n = 0;
            if (rnA < NTOT && lane < KNEI)
                idxA_n = __ldcs(&ij[((size_t)rnA * KNEI + lane) * 2]);
            if (rnB < NTOT && lane < KNEI)
                idxB_n = __ldcs(&ij[((size_t)rnB * KNEI + lane) * 2]);

            uint2 va[KNEI], vb[KNEI];
            #pragma unroll
            for (int k = 0; k < KNEI; k++) {
                int nb = __shfl_sync(0xffffffffu, idxA, k);
                nb = (nb < 0) ? 0 : ((nb >= NTOT) ? (NTOT - 1) : nb);
                va[k] = *(const uint2*)&g_xh[(size_t)nb * XNIN + lane * 4];
            }
            if (rb < NTOT) {
                #pragma unroll
                for (int k = 0; k < KNEI; k++) {
                    int nb = __shfl_sync(0xffffffffu, idxB, k);
                    nb = (nb < 0) ? 0 : ((nb >= NTOT) ? (NTOT - 1) : nb);
                    vb[k] = *(const uint2*)&g_xh[(size_t)nb * XNIN + lane * 4];
                }
            }

            float f0 = 0.f, f1 = 0.f, f2 = 0.f, f3 = 0.f;
            #pragma unroll
            for (int k = 0; k < KNEI; k++) {
                float2 a = __half22float2(*(__half2*)&va[k].x);
                float2 b = __half22float2(*(__half2*)&va[k].y);
                f0 += a.x; f1 += a.y; f2 += b.x; f3 += b.y;
            }
            uint2 gp;
            *(__half2*)&gp.x = __floats2half2_rn(f0 * 0.0625f, f1 * 0.0625f);
            *(__half2*)&gp.y = __floats2half2_rn(f2 * 0.0625f, f3 * 0.0625f);
            *(uint2*)&g_A2[(size_t)r * 192 + lane * 4] = gp;

            if (rb < NTOT) {
                float h0 = 0.f, h1 = 0.f, h2 = 0.f, h3 = 0.f;
                #pragma unroll
                for (int k = 0; k < KNEI; k++) {
                    float2 a = __half22float2(*(__half2*)&vb[k].x);
                    float2 b = __half22float2(*(__half2*)&vb[k].y);
                    h0 += a.x; h1 += a.y; h2 += b.x; h3 += b.y;
                }
                uint2 gq;
                *(__half2*)&gq.x = __floats2half2_rn(h0 * 0.0625f, h1 * 0.0625f);
                *(__half2*)&gq.y = __floats2half2_rn(h2 * 0.0625f, h3 * 0.0625f);
                *(uint2*)&g_A2[(size_t)rb * 192 + lane * 4] = gq;
            }

            idxA = idxA_n; idxB = idxB_n;
        }
    }
}

// ---------------------------------------------------------------------------
// Kernel 3: persistent double-buffered GEMM  out = relu([xh|A2] @ W^T)
// ---------------------------------------------------------------------------
__device__ __forceinline__ uint32_t smem_u32(const void* p) {
    uint32_t a;
    asm("{ .reg .u64 t; cvta.to.shared.u64 t, %1; cvt.u32.u64 %0, t; }"
        : "=r"(a) : "l"(p));
    return a;
}

__device__ __forceinline__ void cp16(uint32_t dst, const void* src) {
    asm volatile("cp.async.cg.shared.global [%0], [%1], 16;"
                 :: "r"(dst), "l"(src));
}

extern __shared__ __half smem[];

__global__ void __launch_bounds__(512, 1)
gemm_kernel(float* __restrict__ out) {
    __half* Wsm = smem;                                   // [128][AS]
    __half* Ab0 = smem + 128 * AS;                        // [64][AS]
    __half* Ab1 = smem + 128 * AS + CHUNK_ROWS * AS;      // [64][AS]
    const uint32_t abase[2] = { smem_u32(Ab0), smem_u32(Ab1) };

    const int tid  = threadIdx.x;
    const int lane = tid & 31;
    const int warp = tid >> 5;

    // ---- W: packed weights -> smem (once per persistent CTA) ----
    {
        const int4* wsrc = (const int4*)g_wh;   // 5120 int4
        for (int i = tid; i < 5120; i += 512) {
            int row = i / 40, c = i % 40;
            *(int4*)&Wsm[row * AS + c * 8] = wsrc[i];
        }
    }

    // ---- prologue: async-load first chunk into buf 0 ----
    int c = blockIdx.x;
    {
        int base = c * CHUNK_ROWS;
        for (int i = tid; i < 2560; i += 512) {        // 64 rows * 40 int4
            int row = i / 40, cc = i % 40;
            int r = base + row; if (r > NTOT - 1) r = NTOT - 1;
            const void* src = (cc < 16)
                ? (const void*)&g_xh[(size_t)r * XNIN + cc * 8]
                : (const void*)&g_A2[(size_t)r * 192 + (cc - 16) * 8];
            cp16(abase[0] + (uint32_t)(row * AS + cc * 8) * 2u, src);
        }
    }
    asm volatile("cp.async.commit_group;" ::: "memory");

    const int g  = lane >> 2;
    const int tg = lane & 3;
    const int mq = warp >> 2;     // 0..3 : 16-row m-tile within chunk
    const int nq = warp & 3;      // 0..3 : 32-col n-quarter
    const int wm = mq * 16;

    int buf = 0;
    for (; c < NCH; c += GRID_G) {
        // ---- prefetch next chunk into the other buffer ----
        int cn = c + GRID_G;
        if (cn < NCH) {
            int base = cn * CHUNK_ROWS;
            for (int i = tid; i < 2560; i += 512) {
                int row = i / 40, cc = i % 40;
                int r = base + row; if (r > NTOT - 1) r = NTOT - 1;
                const void* src = (cc < 16)
                    ? (const void*)&g_xh[(size_t)r * XNIN + cc * 8]
                    : (const void*)&g_A2[(size_t)r * 192 + (cc - 16) * 8];
                cp16(abase[buf ^ 1] + (uint32_t)(row * AS + cc * 8) * 2u, src);
            }
        }
        asm volatile("cp.async.commit_group;" ::: "memory");
        asm volatile("cp.async.wait_group 1;" ::: "memory");   // current buf ready
        __syncthreads();

        // ---- MMA on current buffer ----
        const __half* Asm = (buf == 0) ? Ab0 : Ab1;
        float acc[4][4];
        #pragma unroll
        for (int t = 0; t < 4; t++)
            acc[t][0] = acc[t][1] = acc[t][2] = acc[t][3] = 0.f;

        #pragma unroll 4
        for (int k0 = 0; k0 < KTOT; k0 += 16) {
            uint32_t a0 = *(const uint32_t*)&Asm[(wm + g)     * AS + k0 +     tg * 2];
            uint32_t a1 = *(const uint32_t*)&Asm[(wm + g + 8) * AS + k0 +     tg * 2];
            uint32_t a2 = *(const uint32_t*)&Asm[(wm + g)     * AS + k0 + 8 + tg * 2];
            uint32_t a3 = *(const uint32_t*)&Asm[(wm + g + 8) * AS + k0 + 8 + tg * 2];
            #pragma unroll
            for (int t = 0; t < 4; t++) {
                int nrow = nq * 32 + t * 8 + g;
                uint32_t b0 = *(const uint32_t*)&Wsm[nrow * AS + k0 +     tg * 2];
                uint32_t b1 = *(const uint32_t*)&Wsm[nrow * AS + k0 + 8 + tg * 2];
                asm volatile(
                    "mma.sync.aligned.m16n8k16.row.col.f32.f16.f16.f32 "
                    "{%0,%1,%2,%3},{%4,%5,%6,%7},{%8,%9},{%0,%1,%2,%3};\n"
                    : "+f"(acc[t][0]), "+f"(acc[t][1]), "+f"(acc[t][2]), "+f"(acc[t][3])
                    : "r"(a0), "r"(a1), "r"(a2), "r"(a3), "r"(b0), "r"(b1));
            }
        }

        // ---- store with relu ----
        int rbase = c * CHUNK_ROWS;
        #pragma unroll
        for (int t = 0; t < 4; t++) {
            int col  = nq * 32 + t * 8 + tg * 2;
            int row0 = rbase + wm + g;
            int row1 = row0 + 8;
            if (row0 < NTOT) {
                float2 v;
                v.x = fmaxf(acc[t][0], 0.f);
                v.y = fmaxf(acc[t][1], 0.f);
                __stcs((float2*)&out[(size_t)row0 * XNOUT + col], v);
            }
            if (row1 < NTOT) {
                float2 v;
                v.x = fmaxf(acc[t][2], 0.f);
                v.y = fmaxf(acc[t][3], 0.f);
                __stcs((float2*)&out[(size_t)row1 * XNOUT + col], v);
            }
        }

        __syncthreads();   // all LDS reads of this buffer done before reuse
        buf ^= 1;
    }
}

// ---------------------------------------------------------------------------
extern "C" void kernel_launch(void* const* d_in, const int* in_sizes, int n_in,
                              void* d_out, int out_size) {
    const float* x  = (const float*)d_in[0];
    const float* e  = (const float*)d_in[1];
    const int*   ij = (const int*)d_in[2];     // int32 (JAX x64 disabled)
    const float* Wc = (const float*)d_in[3];
    const float* Wn = (const float*)d_in[4];
    const float* We = (const float*)d_in[5];
    float* out = (float*)d_out;
    (void)in_sizes; (void)n_in; (void)out_size;

    prep_kernel<<<2048, 256>>>(x, Wc, Wn, We);

    build_kernel<<<2048, 256>>>(e, ij);

    const int smem_bytes = (128 + 2 * CHUNK_ROWS) * AS * (int)sizeof(__half); // 167936
    cudaFuncSetAttribute(gemm_kernel,
                         cudaFuncAttributeMaxDynamicSharedMemorySize, smem_bytes);
    gemm_kernel<<<GRID_G, 512, smem_bytes>>>(out);
}

// round 9
// speedup vs baseline: 1.0805x; 1.0805x over previous
#include <cuda_runtime.h>
#include <cuda_fp16.h>
#include <cstdint>

#define NTOT   100000
#define KNEI   16
#define XNIN   128
#define XEIN   64
#define XNOUT  128
#define KTOT   320      // 128 (x) + 128 (xnj) + 64 (xej)
#define AS     328      // smem row stride in halves: bank = 4g+tg, conflict-free
#define CHUNK_ROWS 64
#define NCH    ((NTOT + CHUNK_ROWS - 1) / CHUNK_ROWS)   // 1563
#define GRID_G 152      // GB300: 152 SMs, 1 persistent CTA each

// Scratch (device globals — allocation-free per harness rules)
__device__ __half g_xh[(size_t)NTOT * XNIN];      // fp16 copy of x (25.6 MB)
__device__ __half g_A2[(size_t)NTOT * 192];       // fp16 [gather-mean(128) | e-mean(64)]
__device__ __half g_wh[XNOUT * KTOT];             // packed fp16 [Wc|Wn|We], row-major (n,k)

// ---------------------------------------------------------------------------
// Kernel 1: quantize x -> fp16, pack weights -> fp16
// ---------------------------------------------------------------------------
__global__ void prep_kernel(const float* __restrict__ x,
                            const float* __restrict__ Wc,
                            const float* __restrict__ Wn,
                            const float* __restrict__ We) {
    int tid = blockIdx.x * blockDim.x + threadIdx.x;
    int stride = gridDim.x * blockDim.x;

    const float4* x4 = (const float4*)x;
    __half2* xh2 = (__half2*)g_xh;
    const int total4 = NTOT * XNIN / 4;
    for (int i = tid; i < total4; i += stride) {
        float4 v = __ldcs(&x4[i]);
        xh2[2 * i]     = __floats2half2_rn(v.x, v.y);
        xh2[2 * i + 1] = __floats2half2_rn(v.z, v.w);
    }

    for (int i = tid; i < XNOUT * KTOT; i += stride) {
        int n = i / KTOT, k = i % KTOT;
        float w = (k < 128) ? Wc[n * 128 + k]
                : (k < 256) ? Wn[n * 128 + (k - 128)]
                            : We[n * 64 + (k - 256)];
        g_wh[i] = __float2half(w);
    }
}

// ---------------------------------------------------------------------------
// Kernel 2: build A2 = [ mean_k x_h[nh[r,k]] (128) | mean_k e[r,k,:] (64) ]
// One warp per row, ij software-pipelined. Vectorized: 8x uint4 gathers and
// 8x float4 e-loads per lane with lane-pairing (lane>>4 selects k-parity),
// finished by a shfl_xor(16) reduction. 17 LDGs/row, 512B in flight per lane.
// ---------------------------------------------------------------------------
__global__ void __launch_bounds__(256)
build_kernel(const float* __restrict__ e,
             const int* __restrict__ ij) {
    const int lane   = threadIdx.x & 31;
    const int warpId = (blockIdx.x * blockDim.x + threadIdx.x) >> 5;
    const int nWarps = (gridDim.x * blockDim.x) >> 5;
    const int kg = lane >> 4;        // k parity (0/1)
    const int cg = lane & 15;        // 16B column group

    int r = warpId;
    int idx = 0;
    if (r < NTOT && lane < KNEI)
        idx = __ldcs(&ij[((size_t)r * KNEI + lane) * 2]);

    for (; r < NTOT; r += nWarps) {
        const int rn = r + nWarps;
        int idx_next = 0;
        if (rn < NTOT && lane < KNEI)
            idx_next = __ldcs(&ij[((size_t)rn * KNEI + lane) * 2]);

        // ---- issue all gather loads (8 x uint4 per lane) ----
        uint4 gv[8];
        #pragma unroll
        for (int it = 0; it < 8; it++) {
            int nb = __shfl_sync(0xffffffffu, idx, 2 * it + kg);
            nb = (nb < 0) ? 0 : ((nb >= NTOT) ? (NTOT - 1) : nb);
            gv[it] = *(const uint4*)&g_xh[(size_t)nb * XNIN + cg * 8];
        }

        // ---- issue all e loads (8 x float4 per lane, streaming) ----
        float4 ev[8];
        const float4* ebase = (const float4*)(e + (size_t)r * (KNEI * XEIN));
        #pragma unroll
        for (int it = 0; it < 8; it++)
            ev[it] = __ldcs(ebase + (2 * it + kg) * 16 + cg);

        // ---- gather accumulate (8 half-cols per lane) ----
        float ga[8] = {0.f, 0.f, 0.f, 0.f, 0.f, 0.f, 0.f, 0.f};
        #pragma unroll
        for (int it = 0; it < 8; it++) {
            const __half2* h = (const __half2*)&gv[it];
            #pragma unroll
            for (int j = 0; j < 4; j++) {
                float2 t = __half22float2(h[j]);
                ga[2 * j]     += t.x;
                ga[2 * j + 1] += t.y;
            }
        }
        #pragma unroll
        for (int j = 0; j < 8; j++)
            ga[j] += __shfl_xor_sync(0xffffffffu, ga[j], 16);

        // ---- e accumulate (4 cols per lane) ----
        float e0 = 0.f, e1 = 0.f, e2 = 0.f, e3 = 0.f;
        #pragma unroll
        for (int it = 0; it < 8; it++) {
            e0 += ev[it].x; e1 += ev[it].y; e2 += ev[it].z; e3 += ev[it].w;
        }
        e0 += __shfl_xor_sync(0xffffffffu, e0, 16);
        e1 += __shfl_xor_sync(0xffffffffu, e1, 16);
        e2 += __shfl_xor_sync(0xffffffffu, e2, 16);
        e3 += __shfl_xor_sync(0xffffffffu, e3, 16);

        // ---- stores from lanes 0-15 ----
        if (lane < 16) {
            uint4 gp;
            ((__half2*)&gp)[0] = __floats2half2_rn(ga[0] * 0.0625f, ga[1] * 0.0625f);
            ((__half2*)&gp)[1] = __floats2half2_rn(ga[2] * 0.0625f, ga[3] * 0.0625f);
            ((__half2*)&gp)[2] = __floats2half2_rn(ga[4] * 0.0625f, ga[5] * 0.0625f);
            ((__half2*)&gp)[3] = __floats2half2_rn(ga[6] * 0.0625f, ga[7] * 0.0625f);
            *(uint4*)&g_A2[(size_t)r * 192 + cg * 8] = gp;

            uint2 ep;
            ((__half2*)&ep)[0] = __floats2half2_rn(e0 * 0.0625f, e1 * 0.0625f);
            ((__half2*)&ep)[1] = __floats2half2_rn(e2 * 0.0625f, e3 * 0.0625f);
            *(uint2*)&g_A2[(size_t)r * 192 + 128 + cg * 4] = ep;
        }

        idx = idx_next;
    }
}

// ---------------------------------------------------------------------------
// Kernel 3: persistent double-buffered GEMM  out = relu([xh|A2] @ W^T)
// ---------------------------------------------------------------------------
__device__ __forceinline__ uint32_t smem_u32(const void* p) {
    uint32_t a;
    asm("{ .reg .u64 t; cvta.to.shared.u64 t, %1; cvt.u32.u64 %0, t; }"
        : "=r"(a) : "l"(p));
    return a;
}

__device__ __forceinline__ void cp16(uint32_t dst, const void* src) {
    asm volatile("cp.async.cg.shared.global [%0], [%1], 16;"
                 :: "r"(dst), "l"(src));
}

extern __shared__ __half smem[];

__global__ void __launch_bounds__(512, 1)
gemm_kernel(float* __restrict__ out) {
    __half* Wsm = smem;                                   // [128][AS]
    __half* Ab0 = smem + 128 * AS;                        // [64][AS]
    __half* Ab1 = smem + 128 * AS + CHUNK_ROWS * AS;      // [64][AS]
    const uint32_t abase[2] = { smem_u32(Ab0), smem_u32(Ab1) };

    const int tid  = threadIdx.x;
    const int lane = tid & 31;
    const int warp = tid >> 5;

    // ---- W: packed weights -> smem (once per persistent CTA) ----
    {
        const int4* wsrc = (const int4*)g_wh;   // 5120 int4
        for (int i = tid; i < 5120; i += 512) {
            int row = i / 40, c = i % 40;
            *(int4*)&Wsm[row * AS + c * 8] = wsrc[i];
        }
    }

    // ---- prologue: async-load first chunk into buf 0 ----
    int c = blockIdx.x;
    {
        int base = c * CHUNK_ROWS;
        for (int i = tid; i < 2560; i += 512) {        // 64 rows * 40 int4
            int row = i / 40, cc = i % 40;
            int r = base + row; if (r > NTOT - 1) r = NTOT - 1;
            const void* src = (cc < 16)
                ? (const void*)&g_xh[(size_t)r * XNIN + cc * 8]
                : (const void*)&g_A2[(size_t)r * 192 + (cc - 16) * 8];
            cp16(abase[0] + (uint32_t)(row * AS + cc * 8) * 2u, src);
        }
    }
    asm volatile("cp.async.commit_group;" ::: "memory");

    const int g  = lane >> 2;
    const int tg = lane & 3;
    const int mq = warp >> 2;     // 0..3 : 16-row m-tile within chunk
    const int nq = warp & 3;      // 0..3 : 32-col n-quarter
    const int wm = mq * 16;

    int buf = 0;
    for (; c < NCH; c += GRID_G) {
        // ---- prefetch next chunk into the other buffer ----
        int cn = c + GRID_G;
        if (cn < NCH) {
            int base = cn * CHUNK_ROWS;
            for (int i = tid; i < 2560; i += 512) {
                int row = i / 40, cc = i % 40;
                int r = base + row; if (r > NTOT - 1) r = NTOT - 1;
                const void* src = (cc < 16)
                    ? (const void*)&g_xh[(size_t)r * XNIN + cc * 8]
                    : (const void*)&g_A2[(size_t)r * 192 + (cc - 16) * 8];
                cp16(abase[buf ^ 1] + (uint32_t)(row * AS + cc * 8) * 2u, src);
            }
        }
        asm volatile("cp.async.commit_group;" ::: "memory");
        asm volatile("cp.async.wait_group 1;" ::: "memory");   // current buf ready
        __syncthreads();

        // ---- MMA on current buffer ----
        const __half* Asm = (buf == 0) ? Ab0 : Ab1;
        float acc[4][4];
        #pragma unroll
        for (int t = 0; t < 4; t++)
            acc[t][0] = acc[t][1] = acc[t][2] = acc[t][3] = 0.f;

        #pragma unroll 4
        for (int k0 = 0; k0 < KTOT; k0 += 16) {
            uint32_t a0 = *(const uint32_t*)&Asm[(wm + g)     * AS + k0 +     tg * 2];
            uint32_t a1 = *(const uint32_t*)&Asm[(wm + g + 8) * AS + k0 +     tg * 2];
            uint32_t a2 = *(const uint32_t*)&Asm[(wm + g)     * AS + k0 + 8 + tg * 2];
            uint32_t a3 = *(const uint32_t*)&Asm[(wm + g + 8) * AS + k0 + 8 + tg * 2];
            #pragma unroll
            for (int t = 0; t < 4; t++) {
                int nrow = nq * 32 + t * 8 + g;
                uint32_t b0 = *(const uint32_t*)&Wsm[nrow * AS + k0 +     tg * 2];
                uint32_t b1 = *(const uint32_t*)&Wsm[nrow * AS + k0 + 8 + tg * 2];
                asm volatile(
                    "mma.sync.aligned.m16n8k16.row.col.f32.f16.f16.f32 "
                    "{%0,%1,%2,%3},{%4,%5,%6,%7},{%8,%9},{%0,%1,%2,%3};\n"
                    : "+f"(acc[t][0]), "+f"(acc[t][1]), "+f"(acc[t][2]), "+f"(acc[t][3])
                    : "r"(a0), "r"(a1), "r"(a2), "r"(a3), "r"(b0), "r"(b1));
            }
        }

        // ---- store with relu ----
        int rbase = c * CHUNK_ROWS;
        #pragma unroll
        for (int t = 0; t < 4; t++) {
            int col  = nq * 32 + t * 8 + tg * 2;
            int row0 = rbase + wm + g;
            int row1 = row0 + 8;
            if (row0 < NTOT) {
                float2 v;
                v.x = fmaxf(acc[t][0], 0.f);
                v.y = fmaxf(acc[t][1], 0.f);
                __stcs((float2*)&out[(size_t)row0 * XNOUT + col], v);
            }
            if (row1 < NTOT) {
                float2 v;
                v.x = fmaxf(acc[t][2], 0.f);
                v.y = fmaxf(acc[t][3], 0.f);
                __stcs((float2*)&out[(size_t)row1 * XNOUT + col], v);
            }
        }

        __syncthreads();   // all LDS reads of this buffer done before reuse
        buf ^= 1;
    }
}

// ---------------------------------------------------------------------------
extern "C" void kernel_launch(void* const* d_in, const int* in_sizes, int n_in,
                              void* d_out, int out_size) {
    const float* x  = (const float*)d_in[0];
    const float* e  = (const float*)d_in[1];
    const int*   ij = (const int*)d_in[2];     // int32 (JAX x64 disabled)
    const float* Wc = (const float*)d_in[3];
    const float* Wn = (const float*)d_in[4];
    const float* We = (const float*)d_in[5];
    float* out = (float*)d_out;
    (void)in_sizes; (void)n_in; (void)out_size;

    prep_kernel<<<2048, 256>>>(x, Wc, Wn, We);

    build_kernel<<<2048, 256>>>(e, ij);

    const int smem_bytes = (128 + 2 * CHUNK_ROWS) * AS * (int)sizeof(__half); // 167936
    cudaFuncSetAttribute(gemm_kernel,
                         cudaFuncAttributeMaxDynamicSharedMemorySize, smem_bytes);
    gemm_kernel<<<GRID_G, 512, smem_bytes>>>(out);
}